// round 1
// baseline (speedup 1.0000x reference)
#include <cuda_runtime.h>
#include <cstdint>
#include <cstddef>

// Problem constants
#define B_DIM  8
#define CIN    64
#define COUT   64
#define T_DIM  512
#define F_DIM  161
#define FP     163      // F + 2 (zero-padded halo)
#define TPAD   520      // T + 2 halo, padded to mult of 8 (and >= 516 for over-read)

// ---------------- scratch (device globals; no allocation allowed) -------------
__device__ float g_xT[(size_t)B_DIM * CIN * FP * TPAD];   // ~173.6 MB, x transposed+padded: [b][i][fp][tp]
__device__ float g_wT[(size_t)F_DIM * CIN * 9 * COUT];    // ~23.7 MB,  weights: [f][i][mn][o]

// ---------------- pre-pass 1: transpose/pad x --------------------------------
// xT[b][i][fp][tp] = x[b][i][tp-1][fp-1], zero outside bounds.
__global__ void transpose_x_kernel(const float* __restrict__ x) {
    __shared__ float s[32][33];
    const int bi  = blockIdx.z;            // b*CIN + i
    const int fp0 = blockIdx.x * 32;
    const int tp0 = blockIdx.y * 32;
    const int tx = threadIdx.x, ty = threadIdx.y;

    const float* xs = x + (size_t)bi * T_DIM * F_DIM;
    #pragma unroll
    for (int r = ty; r < 32; r += 8) {
        int t = tp0 + r - 1;
        int f = fp0 + tx - 1;
        float v = 0.f;
        if ((unsigned)t < T_DIM && (unsigned)f < F_DIM) v = xs[t * F_DIM + f];
        s[r][tx] = v;
    }
    __syncthreads();
    float* xd = g_xT + (size_t)bi * FP * TPAD;
    #pragma unroll
    for (int r = ty; r < 32; r += 8) {
        int fp = fp0 + r;
        int tp = tp0 + tx;
        if (fp < FP && tp < TPAD) xd[(size_t)fp * TPAD + tp] = s[tx][r];
    }
}

// ---------------- pre-pass 2: weight layout transform --------------------------
// wT[((f*CIN + i)*9 + mn)*COUT + o] = K[(((o*CIN + i)*F_DIM + f)*9) + mn]
__global__ void transform_w_kernel(const float* __restrict__ k) {
    int idx = blockIdx.x * 256 + threadIdx.x;
    const int total = COUT * CIN * F_DIM * 9;
    if (idx >= total) return;
    int o  = idx & 63;
    int mn = (idx >> 6) % 9;
    int i  = (idx / 576) & 63;
    int f  = idx / (576 * 64);
    g_wT[idx] = k[(((size_t)o * CIN + i) * F_DIM + f) * 9 + mn];
}

// ---------------- main conv kernel --------------------------------------------
// CTA: one (f, b, t-block of 128). Threads 256: warp = o-group (8 o's), lane = t-group (4 t's).
// Per-thread tile: 8 o x 4 t, accumulated as 4 f32x2 pairs (o-paired) x 4 t.

constexpr int ICH       = 16;                 // CIN chunk per smem stage
constexpr int SX_ROW    = 132;                // 130 used, padded to mult of 4 floats (16B align)
constexpr int SX_FLOATS = 3 * ICH * SX_ROW;   // 6336
constexpr int SW_FLOATS = ICH * 9 * 64;       // 9216
constexpr int SMEM_BYTES = (SX_FLOATS + SW_FLOATS) * 4;  // 62208

__device__ __forceinline__ unsigned long long pack_dup(float v) {
    unsigned long long r;
    asm("mov.b64 %0, {%1, %2};" : "=l"(r) : "f"(v), "f"(v));
    return r;
}
__device__ __forceinline__ void fma2(unsigned long long& d,
                                     unsigned long long a,
                                     unsigned long long b) {
    // packed fp32x2 FMA: d = a*b + d  (FFMA2 in SASS, 2x FFMA throughput on Blackwell)
    asm("fma.rn.f32x2 %0, %1, %2, %0;" : "+l"(d) : "l"(a), "l"(b));
}
__device__ __forceinline__ float2 unpack2(unsigned long long v) {
    float2 r;
    asm("mov.b64 {%0, %1}, %2;" : "=f"(r.x), "=f"(r.y) : "l"(v));
    return r;
}

__global__ void __launch_bounds__(256, 2)
conv_main_kernel(const float* __restrict__ bias, float* __restrict__ out) {
    extern __shared__ float smem[];
    float* sx = smem;                 // [fn:3][i:ICH][t:SX_ROW]
    float* sw = smem + SX_FLOATS;     // [i:ICH][mn:9][o:64]

    const int f  = blockIdx.x;
    const int b  = blockIdx.y;
    const int t0 = blockIdx.z * 128;

    const int tid  = threadIdx.x;
    const int og   = tid >> 5;        // warp id = o-group (broadcast-friendly w loads)
    const int lane = tid & 31;        // t-group
    const int tl   = lane * 4;

    unsigned long long acc[4][4];     // [o-pair][t]
    #pragma unroll
    for (int a = 0; a < 4; a++)
        #pragma unroll
        for (int c = 0; c < 4; c++) acc[a][c] = 0ull;

    const float* wsrc_base = g_wT + (size_t)f * CIN * 576;  // 576 = 9*64

    for (int ch = 0; ch < CIN / ICH; ch++) {
        const int ic0 = ch * ICH;
        __syncthreads();   // protect smem of previous chunk

        // ---- stage x tile: 48 rows x 132 floats, float4 streams (fully coalesced) ----
        #pragma unroll
        for (int kk = 0; kk < 7; kk++) {
            int idx = tid + kk * 256;
            if (idx < 48 * 33) {
                int row = idx / 33;
                int q   = idx - row * 33;
                int fn  = row / ICH;
                int i   = row - fn * ICH;
                const float4* src = reinterpret_cast<const float4*>(
                    g_xT + ((size_t)(b * CIN + ic0 + i) * FP + (f + fn)) * TPAD + t0) + q;
                reinterpret_cast<float4*>(sx)[row * 33 + q] = *src;
            }
        }
        // ---- stage w tile: contiguous 9216 floats = 2304 float4 ----
        const float4* wsrc = reinterpret_cast<const float4*>(wsrc_base + (size_t)ic0 * 576);
        #pragma unroll
        for (int kk = 0; kk < 9; kk++) {
            reinterpret_cast<float4*>(sw)[tid + kk * 256] = wsrc[tid + kk * 256];
        }
        __syncthreads();

        // ---- compute ----
        #pragma unroll 2
        for (int i = 0; i < ICH; i++) {
            const float* wrow = sw + (i * 9) * 64 + og * 8;
            #pragma unroll
            for (int n = 0; n < 3; n++) {
                const float* xr = sx + ((n * ICH) + i) * SX_ROW + tl;
                float4 a4 = *reinterpret_cast<const float4*>(xr);
                float2 a2 = *reinterpret_cast<const float2*>(xr + 4);
                unsigned long long xd[6];
                xd[0] = pack_dup(a4.x); xd[1] = pack_dup(a4.y); xd[2] = pack_dup(a4.z);
                xd[3] = pack_dup(a4.w); xd[4] = pack_dup(a2.x); xd[5] = pack_dup(a2.y);
                #pragma unroll
                for (int m = 0; m < 3; m++) {
                    // o-contiguous weights: two 16B broadcast LDS give 4 f32x2 pairs
                    const ulonglong2* wp =
                        reinterpret_cast<const ulonglong2*>(wrow + (m * 3 + n) * 64);
                    ulonglong2 wA = wp[0];   // o pairs {0,1},{2,3}
                    ulonglong2 wB = wp[1];   // o pairs {4,5},{6,7}
                    #pragma unroll
                    for (int tt = 0; tt < 4; tt++) {
                        unsigned long long xs = xd[m + tt];
                        fma2(acc[0][tt], wA.x, xs);
                        fma2(acc[1][tt], wA.y, xs);
                        fma2(acc[2][tt], wB.x, xs);
                        fma2(acc[3][tt], wB.y, xs);
                    }
                }
            }
        }
    }

    // ---- epilogue: add bias, scatter-store (L2 merges the f-strided 4B writes) ----
    #pragma unroll
    for (int op = 0; op < 4; op++) {
        const int o0 = og * 8 + op * 2;
        const float bv0 = __ldg(bias + (o0 + 0) * F_DIM + f);
        const float bv1 = __ldg(bias + (o0 + 1) * F_DIM + f);
        size_t base0 = ((size_t)(b * COUT + o0) * T_DIM + (t0 + tl)) * F_DIM + f;
        size_t base1 = base0 + (size_t)T_DIM * F_DIM;
        #pragma unroll
        for (int tt = 0; tt < 4; tt++) {
            float2 v = unpack2(acc[op][tt]);
            out[base0 + (size_t)tt * F_DIM] = v.x + bv0;
            out[base1 + (size_t)tt * F_DIM] = v.y + bv1;
        }
    }
}

// ---------------- launcher -----------------------------------------------------
extern "C" void kernel_launch(void* const* d_in, const int* in_sizes, int n_in,
                              void* d_out, int out_size) {
    const float* x    = (const float*)d_in[0];
    const float* k    = (const float*)d_in[1];
    const float* bias = (const float*)d_in[2];
    float* out        = (float*)d_out;
    (void)in_sizes; (void)n_in; (void)out_size;

    // opt-in smem (idempotent, not a stream op -> capture-safe)
    cudaFuncSetAttribute((const void*)conv_main_kernel,
                         cudaFuncAttributeMaxDynamicSharedMemorySize, SMEM_BYTES);

    // pre-pass 1: x -> xT (padded, t-contiguous)
    dim3 tb(32, 8);
    dim3 tg((FP + 31) / 32, (TPAD + 31) / 32, B_DIM * CIN);
    transpose_x_kernel<<<tg, tb>>>(x);

    // pre-pass 2: K -> wT [f][i][mn][o]
    const int wtot = COUT * CIN * F_DIM * 9;
    transform_w_kernel<<<(wtot + 255) / 256, 256>>>(k);

    // main conv: grid ordered f-fastest for L2 reuse of xT halos + wT slices
    dim3 grid(F_DIM, B_DIM, T_DIM / 128);
    conv_main_kernel<<<grid, 256, SMEM_BYTES>>>(bias, out);
}

// round 2
// speedup vs baseline: 1.0070x; 1.0070x over previous
#include <cuda_runtime.h>
#include <cstdint>
#include <cstddef>

// Problem constants
#define B_DIM  8
#define CIN    64
#define COUT   64
#define T_DIM  512
#define F_DIM  161
#define FP     163      // F + 2 (zero-padded halo)
#define TPAD   520      // T + 2 halo, padded to mult of 8 (and >= 516 for over-read)

// ---------------- scratch (device globals; no allocation allowed) -------------
__device__ float g_xT[(size_t)B_DIM * CIN * FP * TPAD];   // ~173.6 MB, x transposed+padded: [b][i][fp][tp]
__device__ float g_wT[(size_t)F_DIM * CIN * 9 * COUT];    // ~23.7 MB,  weights: [f][i][mn][o]

// ---------------- pre-pass 1: transpose/pad x --------------------------------
// xT[b][i][fp][tp] = x[b][i][tp-1][fp-1], zero outside bounds.
__global__ void transpose_x_kernel(const float* __restrict__ x) {
    __shared__ float s[32][33];
    const int bi  = blockIdx.z;            // b*CIN + i
    const int fp0 = blockIdx.x * 32;
    const int tp0 = blockIdx.y * 32;
    const int tx = threadIdx.x, ty = threadIdx.y;

    const float* xs = x + (size_t)bi * T_DIM * F_DIM;
    #pragma unroll
    for (int r = ty; r < 32; r += 8) {
        int t = tp0 + r - 1;
        int f = fp0 + tx - 1;
        float v = 0.f;
        if ((unsigned)t < T_DIM && (unsigned)f < F_DIM) v = xs[t * F_DIM + f];
        s[r][tx] = v;
    }
    __syncthreads();
    float* xd = g_xT + (size_t)bi * FP * TPAD;
    #pragma unroll
    for (int r = ty; r < 32; r += 8) {
        int fp = fp0 + r;
        int tp = tp0 + tx;
        if (fp < FP && tp < TPAD) xd[(size_t)fp * TPAD + tp] = s[tx][r];
    }
}

// ---------------- pre-pass 2: weight layout transform --------------------------
// wT[((f*CIN + i)*9 + mn)*COUT + o] = K[(((o*CIN + i)*F_DIM + f)*9) + mn]
__global__ void transform_w_kernel(const float* __restrict__ k) {
    int idx = blockIdx.x * 256 + threadIdx.x;
    const int total = COUT * CIN * F_DIM * 9;
    if (idx >= total) return;
    int o  = idx & 63;
    int mn = (idx >> 6) % 9;
    int i  = (idx / 576) & 63;
    int f  = idx / (576 * 64);
    g_wT[idx] = k[(((size_t)o * CIN + i) * F_DIM + f) * 9 + mn];
}

// ---------------- main conv kernel --------------------------------------------
// CTA: one (f, b, t-block of 128). Threads 256: warp = o-group (8 o's), lane = t-group (4 t's).
// Per-thread tile: 8 o x 4 t, accumulated as 4 f32x2 pairs (o-paired) x 4 t.

constexpr int ICH       = 16;                 // CIN chunk per smem stage
constexpr int SX_ROW    = 132;                // 130 used, padded to mult of 4 floats (16B align)
constexpr int SX_FLOATS = 3 * ICH * SX_ROW;   // 6336
constexpr int SW_FLOATS = ICH * 9 * 64;       // 9216
constexpr int SMEM_BYTES = (SX_FLOATS + SW_FLOATS) * 4;  // 62208

__device__ __forceinline__ unsigned long long pack_dup(float v) {
    unsigned long long r;
    asm("mov.b64 %0, {%1, %2};" : "=l"(r) : "f"(v), "f"(v));
    return r;
}
__device__ __forceinline__ void fma2(unsigned long long& d,
                                     unsigned long long a,
                                     unsigned long long b) {
    // packed fp32x2 FMA: d = a*b + d  (FFMA2 in SASS, 2x FFMA throughput on Blackwell)
    asm("fma.rn.f32x2 %0, %1, %2, %0;" : "+l"(d) : "l"(a), "l"(b));
}
__device__ __forceinline__ float2 unpack2(unsigned long long v) {
    float2 r;
    asm("mov.b64 {%0, %1}, %2;" : "=f"(r.x), "=f"(r.y) : "l"(v));
    return r;
}

__global__ void __launch_bounds__(256, 2)
conv_main_kernel(const float* __restrict__ bias, float* __restrict__ out) {
    extern __shared__ float smem[];
    float* sx = smem;                 // [fn:3][i:ICH][t:SX_ROW]
    float* sw = smem + SX_FLOATS;     // [i:ICH][mn:9][o:64]

    const int f  = blockIdx.x;
    const int b  = blockIdx.y;
    const int t0 = blockIdx.z * 128;

    const int tid  = threadIdx.x;
    const int og   = tid >> 5;        // warp id = o-group (broadcast-friendly w loads)
    const int lane = tid & 31;        // t-group
    const int tl   = lane * 4;

    unsigned long long acc[4][4];     // [o-pair][t]
    #pragma unroll
    for (int a = 0; a < 4; a++)
        #pragma unroll
        for (int c = 0; c < 4; c++) acc[a][c] = 0ull;

    const float* wsrc_base = g_wT + (size_t)f * CIN * 576;  // 576 = 9*64

    for (int ch = 0; ch < CIN / ICH; ch++) {
        const int ic0 = ch * ICH;
        __syncthreads();   // protect smem of previous chunk

        // ---- stage x tile: 48 rows x 132 floats, float4 streams (fully coalesced) ----
        #pragma unroll
        for (int kk = 0; kk < 7; kk++) {
            int idx = tid + kk * 256;
            if (idx < 48 * 33) {
                int row = idx / 33;
                int q   = idx - row * 33;
                int fn  = row / ICH;
                int i   = row - fn * ICH;
                const float4* src = reinterpret_cast<const float4*>(
                    g_xT + ((size_t)(b * CIN + ic0 + i) * FP + (f + fn)) * TPAD + t0) + q;
                reinterpret_cast<float4*>(sx)[row * 33 + q] = *src;
            }
        }
        // ---- stage w tile: contiguous 9216 floats = 2304 float4 ----
        const float4* wsrc = reinterpret_cast<const float4*>(wsrc_base + (size_t)ic0 * 576);
        #pragma unroll
        for (int kk = 0; kk < 9; kk++) {
            reinterpret_cast<float4*>(sw)[tid + kk * 256] = wsrc[tid + kk * 256];
        }
        __syncthreads();

        // ---- compute ----
        #pragma unroll 2
        for (int i = 0; i < ICH; i++) {
            const float* wrow = sw + (i * 9) * 64 + og * 8;
            #pragma unroll
            for (int n = 0; n < 3; n++) {
                const float* xr = sx + ((n * ICH) + i) * SX_ROW + tl;
                float4 a4 = *reinterpret_cast<const float4*>(xr);
                float2 a2 = *reinterpret_cast<const float2*>(xr + 4);
                unsigned long long xd[6];
                xd[0] = pack_dup(a4.x); xd[1] = pack_dup(a4.y); xd[2] = pack_dup(a4.z);
                xd[3] = pack_dup(a4.w); xd[4] = pack_dup(a2.x); xd[5] = pack_dup(a2.y);
                #pragma unroll
                for (int m = 0; m < 3; m++) {
                    // o-contiguous weights: two 16B broadcast LDS give 4 f32x2 pairs
                    const ulonglong2* wp =
                        reinterpret_cast<const ulonglong2*>(wrow + (m * 3 + n) * 64);
                    ulonglong2 wA = wp[0];   // o pairs {0,1},{2,3}
                    ulonglong2 wB = wp[1];   // o pairs {4,5},{6,7}
                    #pragma unroll
                    for (int tt = 0; tt < 4; tt++) {
                        unsigned long long xs = xd[m + tt];
                        fma2(acc[0][tt], wA.x, xs);
                        fma2(acc[1][tt], wA.y, xs);
                        fma2(acc[2][tt], wB.x, xs);
                        fma2(acc[3][tt], wB.y, xs);
                    }
                }
            }
        }
    }

    // ---- epilogue: add bias, scatter-store (L2 merges the f-strided 4B writes) ----
    #pragma unroll
    for (int op = 0; op < 4; op++) {
        const int o0 = og * 8 + op * 2;
        const float bv0 = __ldg(bias + (o0 + 0) * F_DIM + f);
        const float bv1 = __ldg(bias + (o0 + 1) * F_DIM + f);
        size_t base0 = ((size_t)(b * COUT + o0) * T_DIM + (t0 + tl)) * F_DIM + f;
        size_t base1 = base0 + (size_t)T_DIM * F_DIM;
        #pragma unroll
        for (int tt = 0; tt < 4; tt++) {
            float2 v = unpack2(acc[op][tt]);
            out[base0 + (size_t)tt * F_DIM] = v.x + bv0;
            out[base1 + (size_t)tt * F_DIM] = v.y + bv1;
        }
    }
}

// ---------------- launcher -----------------------------------------------------
extern "C" void kernel_launch(void* const* d_in, const int* in_sizes, int n_in,
                              void* d_out, int out_size) {
    const float* x    = (const float*)d_in[0];
    const float* k    = (const float*)d_in[1];
    const float* bias = (const float*)d_in[2];
    float* out        = (float*)d_out;
    (void)in_sizes; (void)n_in; (void)out_size;

    // opt-in smem (idempotent, not a stream op -> capture-safe)
    cudaFuncSetAttribute((const void*)conv_main_kernel,
                         cudaFuncAttributeMaxDynamicSharedMemorySize, SMEM_BYTES);

    // pre-pass 1: x -> xT (padded, t-contiguous)
    dim3 tb(32, 8);
    dim3 tg((FP + 31) / 32, (TPAD + 31) / 32, B_DIM * CIN);
    transpose_x_kernel<<<tg, tb>>>(x);

    // pre-pass 2: K -> wT [f][i][mn][o]
    const int wtot = COUT * CIN * F_DIM * 9;
    transform_w_kernel<<<(wtot + 255) / 256, 256>>>(k);

    // main conv: grid ordered f-fastest for L2 reuse of xT halos + wT slices
    dim3 grid(F_DIM, B_DIM, T_DIM / 128);
    conv_main_kernel<<<grid, 256, SMEM_BYTES>>>(bias, out);
}